// round 11
// baseline (speedup 1.0000x reference)
#include <cuda_runtime.h>

#define NN   100000
#define EE   3200000
#define KORD 10
#define CC   64
#define FIN  512

// ---------------- scratch (static __device__, per allocation rules) -------------
__device__ int   d_deg[NN];
__device__ int   d_rowptr[NN + 1];
__device__ int   d_cursor[NN];
__device__ int   d_blk[128];
__device__ float d_dinv[NN];
__device__ int   d_srcs[EE];
__device__ float d_norms[EE];
__device__ float d_P[3][NN * CC];   // rotating Chebyshev buffers (P0 = h in slot 0)
__device__ float d_acc[NN * CC];    // weighted combine accumulator

// ---------------- CSR build ----------------------------------------------------
__global__ void k_zero_deg() {
    int i = blockIdx.x * blockDim.x + threadIdx.x;
    if (i < NN) d_deg[i] = 0;
}

__global__ void k_count(const int* __restrict__ ei) {
    int e = blockIdx.x * blockDim.x + threadIdx.x;
    if (e < EE) atomicAdd(&d_deg[ei[EE + e]], 1);
}

__global__ void k_scan1() {
    __shared__ int sh[1024];
    int i = blockIdx.x * 1024 + threadIdx.x;
    int v = (i < NN) ? d_deg[i] : 0;
    sh[threadIdx.x] = v;
    __syncthreads();
    for (int off = 1; off < 1024; off <<= 1) {
        int t = (threadIdx.x >= off) ? sh[threadIdx.x - off] : 0;
        __syncthreads();
        sh[threadIdx.x] += t;
        __syncthreads();
    }
    if (i < NN) d_rowptr[i] = sh[threadIdx.x] - v;     // block-local exclusive
    if (threadIdx.x == 1023) d_blk[blockIdx.x] = sh[1023];
}

__global__ void k_scan2(int nblk) {
    if (blockIdx.x == 0 && threadIdx.x == 0) {
        int run = 0;
        for (int i = 0; i < nblk; i++) { int v = d_blk[i]; d_blk[i] = run; run += v; }
    }
}

__global__ void k_scan3() {
    int i = blockIdx.x * blockDim.x + threadIdx.x;
    if (i < NN) {
        int rp = d_rowptr[i] + d_blk[i >> 10];
        d_rowptr[i] = rp;
        d_cursor[i] = rp;
        int dg = d_deg[i];
        d_dinv[i] = (dg > 0) ? rsqrtf((float)dg) : 1.0f;
    }
    if (i == 0) d_rowptr[NN] = EE;
}

__global__ void k_scatter(const int* __restrict__ ei) {
    int e = blockIdx.x * blockDim.x + threadIdx.x;
    if (e < EE) {
        int r = ei[e];
        int c = ei[EE + e];
        int p = atomicAdd(&d_cursor[c], 1);
        d_srcs[p]  = r;
        d_norms[p] = d_dinv[r] * d_dinv[c];
    }
}

// ---------------- GEMM: h = x @ W + b, fused acc init (coef0 = 1) ---------------
// 64x64 tile, 256 threads, 4x4 microtile, K-tile 32.
__global__ __launch_bounds__(256) void k_gemm(const float* __restrict__ x,
                                              const float* __restrict__ W,
                                              const float* __restrict__ bias,
                                              const float* __restrict__ mfw) {
    __shared__ float xsT[32][68];   // [k][m], padded
    __shared__ float Ws[32][64];    // [k][c]
    int tid = threadIdx.x;
    int m0  = blockIdx.x * 64;
    int ty  = tid >> 4, tx = tid & 15;

    float acc[4][4];
#pragma unroll
    for (int i = 0; i < 4; i++)
#pragma unroll
        for (int j = 0; j < 4; j++) acc[i][j] = 0.f;

    for (int k0 = 0; k0 < FIN; k0 += 32) {
#pragma unroll
        for (int it = 0; it < 2; ++it) {
            int idx = tid + it * 256;
            int row = idx >> 3, fc = idx & 7;
            float4 v = make_float4(0.f, 0.f, 0.f, 0.f);
            int gr = m0 + row;
            if (gr < NN) v = *(const float4*)(x + (long)gr * FIN + k0 + fc * 4);
            xsT[fc * 4 + 0][row] = v.x;
            xsT[fc * 4 + 1][row] = v.y;
            xsT[fc * 4 + 2][row] = v.z;
            xsT[fc * 4 + 3][row] = v.w;
        }
#pragma unroll
        for (int it = 0; it < 2; ++it) {
            int idx = tid + it * 256;
            int kr = idx >> 4, fc = idx & 15;
            *(float4*)&Ws[kr][fc * 4] = *(const float4*)(W + (k0 + kr) * CC + fc * 4);
        }
        __syncthreads();
#pragma unroll
        for (int kk = 0; kk < 32; ++kk) {
            float4 a  = *(const float4*)&xsT[kk][ty * 4];
            float4 bb = *(const float4*)&Ws[kk][tx * 4];
            acc[0][0] += a.x * bb.x; acc[0][1] += a.x * bb.y; acc[0][2] += a.x * bb.z; acc[0][3] += a.x * bb.w;
            acc[1][0] += a.y * bb.x; acc[1][1] += a.y * bb.y; acc[1][2] += a.y * bb.z; acc[1][3] += a.y * bb.w;
            acc[2][0] += a.z * bb.x; acc[2][1] += a.z * bb.y; acc[2][2] += a.z * bb.z; acc[2][3] += a.z * bb.w;
            acc[3][0] += a.w * bb.x; acc[3][1] += a.w * bb.y; acc[3][2] += a.w * bb.z; acc[3][3] += a.w * bb.w;
        }
        __syncthreads();
    }

    float4 b4 = *(const float4*)(bias + tx * 4);
    float4 w0 = *(const float4*)(mfw + tx * 4);   // mf_weights[0][c], coef0 = 1
#pragma unroll
    for (int i = 0; i < 4; i++) {
        int row = m0 + ty * 4 + i;
        if (row < NN) {
            float h0 = acc[i][0] + b4.x;
            float h1 = acc[i][1] + b4.y;
            float h2 = acc[i][2] + b4.z;
            float h3 = acc[i][3] + b4.w;
            *(float4*)(&d_P[0][(long)row * CC + tx * 4]) = make_float4(h0, h1, h2, h3);
            *(float4*)(&d_acc[(long)row * CC + tx * 4]) =
                make_float4(h0 * w0.x, h1 * w0.y, h2 * w0.z, h3 * w0.w);
        }
    }
}

// ---------------- fused propagate + recurrence + weighted accumulate ------------
// One warp per node; lane handles cols (2l, 2l+1). n>=1.
//   t = prop(P[inb]);  Pn = (n>=2 ? 2t - P[pb] : t);
//   acc += lap[n-1] * mfw[n][c] * Pn
// Final iteration (n==KORD): skip P/acc stores, compute log_softmax in-warp,
// write directly to out.
__global__ __launch_bounds__(256) void k_prop(int n, int inb, int outb, int pb,
                                              const float* __restrict__ lap,
                                              const float* __restrict__ mfw,
                                              float* __restrict__ out) {
    int gw   = (blockIdx.x * blockDim.x + threadIdx.x) >> 5;
    int lane = threadIdx.x & 31;
    if (gw >= NN) return;
    const float* __restrict__ Pin = d_P[inb];
    int beg = d_rowptr[gw], end = d_rowptr[gw + 1];
    int c2  = 2 * lane;

    float sx = 0.f, sy = 0.f;
    int p = beg;
    for (; p + 4 <= end; p += 4) {
        int   s0 = d_srcs[p],     s1 = d_srcs[p + 1], s2 = d_srcs[p + 2], s3 = d_srcs[p + 3];
        float n0 = d_norms[p],    n1 = d_norms[p + 1], n2 = d_norms[p + 2], n3 = d_norms[p + 3];
        float2 v0 = *(const float2*)(Pin + (long)s0 * CC + c2);
        float2 v1 = *(const float2*)(Pin + (long)s1 * CC + c2);
        float2 v2 = *(const float2*)(Pin + (long)s2 * CC + c2);
        float2 v3 = *(const float2*)(Pin + (long)s3 * CC + c2);
        sx += n0 * v0.x + n1 * v1.x + n2 * v2.x + n3 * v3.x;
        sy += n0 * v0.y + n1 * v1.y + n2 * v2.y + n3 * v3.y;
    }
    for (; p < end; ++p) {
        int   s  = d_srcs[p];
        float nm = d_norms[p];
        float2 v = *(const float2*)(Pin + (long)s * CC + c2);
        sx += nm * v.x;
        sy += nm * v.y;
    }

    float px, py;
    if (n >= 2) {
        float2 q = *(const float2*)(d_P[pb] + (long)gw * CC + c2);
        px = 2.f * sx - q.x;
        py = 2.f * sy - q.y;
    } else {
        px = sx; py = sy;
    }

    float coef = lap[n - 1];
    float w0 = coef * mfw[n * CC + c2];
    float w1 = coef * mfw[n * CC + c2 + 1];
    float2 a = *(const float2*)(d_acc + (long)gw * CC + c2);
    a.x += w0 * px;
    a.y += w1 * py;

    if (n < KORD) {
        *(float2*)(d_P[outb] + (long)gw * CC + c2) = make_float2(px, py);
        *(float2*)(d_acc + (long)gw * CC + c2) = a;
    } else {
        // fused log_softmax over the warp-held 64-wide row
        float m = fmaxf(a.x, a.y);
#pragma unroll
        for (int o = 16; o; o >>= 1) m = fmaxf(m, __shfl_xor_sync(0xffffffffu, m, o));
        float s = expf(a.x - m) + expf(a.y - m);
#pragma unroll
        for (int o = 16; o; o >>= 1) s += __shfl_xor_sync(0xffffffffu, s, o);
        float l = m + logf(s);
        *(float2*)(out + (long)gw * CC + c2) = make_float2(a.x - l, a.y - l);
    }
}

// ---------------- launch --------------------------------------------------------
extern "C" void kernel_launch(void* const* d_in, const int* in_sizes, int n_in,
                              void* d_out, int out_size) {
    const float* x   = (const float*)d_in[0];
    const int*   ei  = (const int*)d_in[1];     // int32 (JAX default x64-disabled)
    const float* W   = (const float*)d_in[2];
    const float* b   = (const float*)d_in[3];
    const float* lap = (const float*)d_in[4];
    const float* mfw = (const float*)d_in[5];
    float*       out = (float*)d_out;

    (void)in_sizes; (void)n_in; (void)out_size;

    k_zero_deg<<<(NN + 255) / 256, 256>>>();
    k_count<<<(EE + 255) / 256, 256>>>(ei);
    int nblk = (NN + 1023) / 1024;   // 98
    k_scan1<<<nblk, 1024>>>();
    k_scan2<<<1, 32>>>(nblk);
    k_scan3<<<(NN + 255) / 256, 256>>>();
    k_scatter<<<(EE + 255) / 256, 256>>>(ei);

    k_gemm<<<(NN + 63) / 64, 256>>>(x, W, b, mfw);

    // warps = NN, 8 warps/block
    int prop_blocks = (NN + 7) / 8;
    for (int n = 1; n <= KORD; n++) {
        int inb  = (n - 1) % 3;
        int outb = n % 3;
        int pb   = (n + 1) % 3;   // == (n-2) mod 3
        k_prop<<<prop_blocks, 256>>>(n, inb, outb, pb, lap, mfw, out);
    }
}